// round 9
// baseline (speedup 1.0000x reference)
#include <cuda_runtime.h>
#include <cuda_fp16.h>
#include <math.h>

#define B_DIM      256
#define B_HALF2    (B_DIM / 2)       // 128 half2 (uint) per A_T row = 512 B
#define NB_DIM     50000
#define N_CYC      20000
#define P2_THREADS 128               // thread = one half2 lane of the row
#define P2_BASE    64                // entries owned per phase-2 block
#define P2_EXT     160               // staged entries (64 + 96 slack)

// A_T[i] = 256 batch angles as fp16; row i = 128 uints (half2), 512 B.
__device__ unsigned g_ATu[(size_t)NB_DIM * B_HALF2];   // 25.6 MB
__device__ double   g_accum;
__device__ unsigned g_done;

// ---------------------------------------------------------------------------
// Branchless fast atan2 (minimax, |err| < 1e-5 rad; subdominant to fp16
// storage quantization).
// ---------------------------------------------------------------------------
__device__ __forceinline__ float fast_atan2f(float y, float x) {
    const float ax = fabsf(x), ay = fabsf(y);
    const float mx = fmaxf(ax, ay), mn = fminf(ax, ay);
    const float t = __fdividef(mn, mx);
    const float a = t * t;
    float r = fmaf(a, 0.0208351f, -0.0851330f);
    r = fmaf(r, a, 0.1801410f);
    r = fmaf(r, a, -0.3302995f);
    r = fmaf(r, a, 0.9998660f);
    r = r * t;
    if (ay > ax)  r = 1.57079632679f - r;
    if (x < 0.0f) r = 3.14159265359f - r;
    return copysignf(r, y);
}

__device__ __forceinline__ unsigned pack_pair(float a, float b) {
    __half2 h = __floats2half2_rn(a, b);
    return *reinterpret_cast<unsigned*>(&h);
}

// ---------------------------------------------------------------------------
// Phase 1: A_T[i][b] = (half)atan2(s[b,i], c[b,i]).
// Tile 64 i x 64 b, block (16,16): thread handles i-quad x TWO batch-pairs
// (8x LDG.128 front-batched, 16 atan2). c/s loaded streaming (__ldcs) so
// they don't evict A_T from L2. Transpose via smem, coalesced 128B rows out.
// ---------------------------------------------------------------------------
__global__ void phase1_atan2_transpose(const float* __restrict__ c,
                                       const float* __restrict__ s) {
    __shared__ unsigned tile[64][33];

    const int tx = threadIdx.x;          // 0..15 : i-quad
    const int ty = threadIdx.y;          // 0..15 : base b-pair
    const int i_base = blockIdx.x * 64;
    const int b_base = blockIdx.y * 64;
    const int i0 = i_base + tx * 4;

    if (i0 < NB_DIM) {                   // i0%4==0, NB_DIM%4==0 -> safe float4
        const int bA = b_base + 2 * ty;          // pair A: batches bA, bA+1
        const int bB = b_base + 2 * (ty + 16);   // pair B

        const float4* cp = (const float4*)(c + i0);
        const float4* sp = (const float4*)(s + i0);
        const size_t q = (size_t)NB_DIM / 4;

        const float4 cA1 = __ldcs(cp + (size_t)bA * q);
        const float4 sA1 = __ldcs(sp + (size_t)bA * q);
        const float4 cA2 = __ldcs(cp + (size_t)(bA + 1) * q);
        const float4 sA2 = __ldcs(sp + (size_t)(bA + 1) * q);
        const float4 cB1 = __ldcs(cp + (size_t)bB * q);
        const float4 sB1 = __ldcs(sp + (size_t)bB * q);
        const float4 cB2 = __ldcs(cp + (size_t)(bB + 1) * q);
        const float4 sB2 = __ldcs(sp + (size_t)(bB + 1) * q);

        tile[tx*4+0][ty]    = pack_pair(fast_atan2f(sA1.x, cA1.x), fast_atan2f(sA2.x, cA2.x));
        tile[tx*4+1][ty]    = pack_pair(fast_atan2f(sA1.y, cA1.y), fast_atan2f(sA2.y, cA2.y));
        tile[tx*4+2][ty]    = pack_pair(fast_atan2f(sA1.z, cA1.z), fast_atan2f(sA2.z, cA2.z));
        tile[tx*4+3][ty]    = pack_pair(fast_atan2f(sA1.w, cA1.w), fast_atan2f(sA2.w, cA2.w));
        tile[tx*4+0][ty+16] = pack_pair(fast_atan2f(sB1.x, cB1.x), fast_atan2f(sB2.x, cB2.x));
        tile[tx*4+1][ty+16] = pack_pair(fast_atan2f(sB1.y, cB1.y), fast_atan2f(sB2.y, cB2.y));
        tile[tx*4+2][ty+16] = pack_pair(fast_atan2f(sB1.z, cB1.z), fast_atan2f(sB2.z, cB2.z));
        tile[tx*4+3][ty+16] = pack_pair(fast_atan2f(sB1.w, cB1.w), fast_atan2f(sB2.w, cB2.w));
    }
    __syncthreads();

    // 8 warps x 8 rows: coalesced 32-uint (128B) row writes.
    const int tid  = ty * 16 + tx;
    const int w    = tid >> 5;
    const int lane = tid & 31;
    #pragma unroll
    for (int k = 0; k < 8; ++k) {
        const int r  = w + 8 * k;
        const int gi = i_base + r;
        if (gi < NB_DIM)
            g_ATu[(size_t)gi * B_HALF2 + (b_base >> 1) + lane] = tile[r][lane];
    }

    if (blockIdx.x == 0 && blockIdx.y == 0 && tid == 0) {
        g_accum = 0.0;
        g_done = 0u;
    }
}

// ---------------------------------------------------------------------------
// Phase 2: entry-partitioned (64 entries/block), 128 threads = one half2
// lane each (full occupancy: 2500 blocks x 4 warps ~= 64 warps/SM).
// Stage window with row-change flags; inner loop per entry per thread:
// LDS(broadcast) + LDG.32 + XOR(sign) + HADD2, unroll 8 for MLP.
// Last block writes the final scalar.
// ---------------------------------------------------------------------------
__global__ __launch_bounds__(P2_THREADS) void phase2_cycle_sum(
    const float* __restrict__ cysigns,
    const int*   __restrict__ cyinds,
    const int*   __restrict__ cyrows,
    float*       __restrict__ out,
    int E) {

    __shared__ uint2 sh[P2_EXT];
    __shared__ int   sh_se[2];
    __shared__ float warp_sums[P2_THREADS / 32];

    const int tid  = threadIdx.x;
    const int base = blockIdx.x * P2_BASE;
    const int n    = min(P2_EXT, E - base);

    // Stage: .x = idx*128 | rowchange<<31, .y = sign xor-mask for half2.
    for (int j = tid; j < n; j += P2_THREADS) {
        const int e = base + j;
        const int idx = __ldg(&cyinds[e]);
        unsigned m = __float_as_uint(__ldg(&cysigns[e])) & 0x80000000u;
        m |= m >> 16;
        const int row  = __ldg(&cyrows[e]);
        const int prev = (e > 0) ? __ldg(&cyrows[e - 1]) : -1;
        const unsigned flag = (row != prev) ? 0x80000000u : 0u;
        sh[j] = make_uint2((unsigned)(idx * B_HALF2) | flag, m);
    }
    __syncthreads();

    if (tid == 0) {
        int st = 0;
        while (st < n && !(sh[st].x & 0x80000000u)) ++st;
        int en = (P2_BASE < n) ? P2_BASE : n;
        while (en < n && !(sh[en].x & 0x80000000u)) ++en;
        sh_se[0] = st;
        sh_se[1] = en;
    }
    __syncthreads();
    const int st = sh_se[0];
    const int en = sh_se[1];

    const __half2 h2z = __half2half2(__ushort_as_half(0));
    __half2 acc = h2z;
    float sum = 0.0f;

    #pragma unroll 8
    for (int j = st; j < en; ++j) {
        const uint2 p = sh[j];
        if (p.x & 0x80000000u) {             // uniform across block
            const float2 f = __half22float2(acc);
            sum += fabsf(f.x) + fabsf(f.y);
            acc = h2z;
        }
        unsigned u = g_ATu[(size_t)(p.x & 0x7FFFFFFFu) + tid];
        u ^= p.y;
        acc = __hadd2(acc, *reinterpret_cast<__half2*>(&u));
    }

    // Fallback (statistically never taken): the block's last row extends
    // beyond the staged window -> finish it straight from global memory.
    if (en == n && st < en && base + n < E) {
        const int row = __ldg(&cyrows[base + n - 1]);
        for (int e = base + n; e < E && __ldg(&cyrows[e]) == row; ++e) {
            const int idx = __ldg(&cyinds[e]);
            unsigned m = __float_as_uint(__ldg(&cysigns[e])) & 0x80000000u;
            m |= m >> 16;
            unsigned u = g_ATu[(size_t)idx * B_HALF2 + tid];
            u ^= m;
            acc = __hadd2(acc, *reinterpret_cast<__half2*>(&u));
        }
    }

    {   // final row flush
        const float2 f = __half22float2(acc);
        sum += fabsf(f.x) + fabsf(f.y);
    }

    // Block reduction (4 warps)
    #pragma unroll
    for (int off = 16; off > 0; off >>= 1)
        sum += __shfl_down_sync(0xFFFFFFFFu, sum, off);
    const int lane = tid & 31, wid = tid >> 5;
    if (lane == 0) warp_sums[wid] = sum;
    __syncthreads();
    if (tid == 0) {
        const float w = warp_sums[0] + warp_sums[1] + warp_sums[2] + warp_sums[3];
        if (w != 0.0f) atomicAdd(&g_accum, (double)w);
        __threadfence();
        const unsigned ticket = atomicAdd(&g_done, 1u);
        if (ticket == (unsigned)(gridDim.x - 1)) {
            __threadfence();
            const double total = *((volatile double*)&g_accum);
            out[0] = (float)(total * (1.0 / ((double)N_CYC * (double)B_DIM)));
        }
    }
}

extern "C" void kernel_launch(void* const* d_in, const int* in_sizes, int n_in,
                              void* d_out, int out_size) {
    const float* c       = (const float*)d_in[0];
    const float* s       = (const float*)d_in[1];
    const float* cysigns = (const float*)d_in[2];
    const int*   cyinds  = (const int*)d_in[3];
    const int*   cyrows  = (const int*)d_in[4];
    float* out = (float*)d_out;
    const int E = in_sizes[4];

    dim3 t1(16, 16);
    dim3 g1((NB_DIM + 63) / 64, B_DIM / 64);
    phase1_atan2_transpose<<<g1, t1>>>(c, s);

    const int g2 = (E + P2_BASE - 1) / P2_BASE;
    phase2_cycle_sum<<<g2, P2_THREADS>>>(cysigns, cyinds, cyrows, out, E);
}

// round 11
// speedup vs baseline: 1.0062x; 1.0062x over previous
#include <cuda_runtime.h>
#include <cuda_fp16.h>
#include <math.h>

#define B_DIM      256
#define B_HALF2    (B_DIM / 2)       // 128 uints per A_T row = 512 B
#define B_UINT4    32                // 32 uint4 per row
#define NB_DIM     50000
#define N_CYC      20000
#define P2_THREADS 64                // 2 warps; warp = one full row (32 x uint4)
#define P2_BASE    32                // entries owned per phase-2 block
#define P2_EXT     128               // staged window (32 owned + 96 slack)

// A_T[i] = 256 batch angles as fp16; row i = 32 uint4 = 512 B.
__device__ uint4    g_AT4[(size_t)NB_DIM * B_UINT4];   // 25.6 MB
__device__ double   g_accum;
__device__ unsigned g_done;

// ---------------------------------------------------------------------------
// Branchless fast atan2 (minimax, |err| < 1e-5 rad; subdominant to fp16
// storage quantization).
// ---------------------------------------------------------------------------
__device__ __forceinline__ float fast_atan2f(float y, float x) {
    const float ax = fabsf(x), ay = fabsf(y);
    const float mx = fmaxf(ax, ay), mn = fminf(ax, ay);
    const float t = __fdividef(mn, mx);
    const float a = t * t;
    float r = fmaf(a, 0.0208351f, -0.0851330f);
    r = fmaf(r, a, 0.1801410f);
    r = fmaf(r, a, -0.3302995f);
    r = fmaf(r, a, 0.9998660f);
    r = r * t;
    if (ay > ax)  r = 1.57079632679f - r;
    if (x < 0.0f) r = 3.14159265359f - r;
    return copysignf(r, y);
}

__device__ __forceinline__ unsigned pack_pair(float a, float b) {
    __half2 h = __floats2half2_rn(a, b);
    return *reinterpret_cast<unsigned*>(&h);
}

// ---------------------------------------------------------------------------
// Phase 1: A_T[i][b] = (half)atan2(s[b,i], c[b,i]).
// Tile 64 i x 64 b, block (16,16): thread handles i-quad x TWO batch-pairs
// (8x LDG.128 front-batched, 16 atan2). c/s loaded streaming (__ldcs) so
// they don't evict A_T from L2. Transpose via smem, coalesced 128B rows out.
// ---------------------------------------------------------------------------
__global__ void phase1_atan2_transpose(const float* __restrict__ c,
                                       const float* __restrict__ s) {
    __shared__ unsigned tile[64][33];

    const int tx = threadIdx.x;          // 0..15 : i-quad
    const int ty = threadIdx.y;          // 0..15 : base b-pair
    const int i_base = blockIdx.x * 64;
    const int b_base = blockIdx.y * 64;
    const int i0 = i_base + tx * 4;

    if (i0 < NB_DIM) {                   // i0%4==0, NB_DIM%4==0 -> safe float4
        const int bA = b_base + 2 * ty;
        const int bB = b_base + 2 * (ty + 16);

        const float4* cp = (const float4*)(c + i0);
        const float4* sp = (const float4*)(s + i0);
        const size_t q = (size_t)NB_DIM / 4;

        const float4 cA1 = __ldcs(cp + (size_t)bA * q);
        const float4 sA1 = __ldcs(sp + (size_t)bA * q);
        const float4 cA2 = __ldcs(cp + (size_t)(bA + 1) * q);
        const float4 sA2 = __ldcs(sp + (size_t)(bA + 1) * q);
        const float4 cB1 = __ldcs(cp + (size_t)bB * q);
        const float4 sB1 = __ldcs(sp + (size_t)bB * q);
        const float4 cB2 = __ldcs(cp + (size_t)(bB + 1) * q);
        const float4 sB2 = __ldcs(sp + (size_t)(bB + 1) * q);

        tile[tx*4+0][ty]    = pack_pair(fast_atan2f(sA1.x, cA1.x), fast_atan2f(sA2.x, cA2.x));
        tile[tx*4+1][ty]    = pack_pair(fast_atan2f(sA1.y, cA1.y), fast_atan2f(sA2.y, cA2.y));
        tile[tx*4+2][ty]    = pack_pair(fast_atan2f(sA1.z, cA1.z), fast_atan2f(sA2.z, cA2.z));
        tile[tx*4+3][ty]    = pack_pair(fast_atan2f(sA1.w, cA1.w), fast_atan2f(sA2.w, cA2.w));
        tile[tx*4+0][ty+16] = pack_pair(fast_atan2f(sB1.x, cB1.x), fast_atan2f(sB2.x, cB2.x));
        tile[tx*4+1][ty+16] = pack_pair(fast_atan2f(sB1.y, cB1.y), fast_atan2f(sB2.y, cB2.y));
        tile[tx*4+2][ty+16] = pack_pair(fast_atan2f(sB1.z, cB1.z), fast_atan2f(sB2.z, cB2.z));
        tile[tx*4+3][ty+16] = pack_pair(fast_atan2f(sB1.w, cB1.w), fast_atan2f(sB2.w, cB2.w));
    }
    __syncthreads();

    const int tid  = ty * 16 + tx;
    const int w    = tid >> 5;
    const int lane = tid & 31;
    unsigned* ATu = (unsigned*)g_AT4;
    #pragma unroll
    for (int k = 0; k < 8; ++k) {
        const int r  = w + 8 * k;
        const int gi = i_base + r;
        if (gi < NB_DIM)
            ATu[(size_t)gi * B_HALF2 + (b_base >> 1) + lane] = tile[r][lane];
    }

    if (blockIdx.x == 0 && blockIdx.y == 0 && tid == 0) {
        g_accum = 0.0;
        g_done = 0u;
    }
}

// ---------------------------------------------------------------------------
// Phase 2: entry-partitioned, 32 entries owned per block, 64 threads.
// Stage 128-entry window as packed meta: idx*32 | sign<<29 | rowchange<<31.
// Warp-ballot scan extracts row starts; each WARP processes whole rows
// (round-robin), thread = one uint4 lane of the 512B row -> per entry exactly
// one LDG.128 per warp. |.| flush is warp-local at row end.
// Last block writes the final scalar.
// ---------------------------------------------------------------------------
__global__ __launch_bounds__(P2_THREADS) void phase2_cycle_sum(
    const float* __restrict__ cysigns,
    const int*   __restrict__ cyinds,
    const int*   __restrict__ cyrows,
    float*       __restrict__ out,
    int E) {

    __shared__ unsigned sh[P2_EXT];      // packed meta
    __shared__ short    rs[P2_EXT + 1];  // row-start positions in window
    __shared__ int      sh_cnt[2];       // {m_total_starts, m_owned}
    __shared__ float    warp_sums[2];

    const int tid  = threadIdx.x;
    const int lane = tid & 31;
    const int wid  = tid >> 5;
    const int base = blockIdx.x * P2_BASE;
    const int n    = min(P2_EXT, E - base);

    // Stage meta.
    for (int j = tid; j < n; j += P2_THREADS) {
        const int e = base + j;
        const int idx = __ldg(&cyinds[e]);
        const unsigned sbit = __float_as_uint(__ldg(&cysigns[e])) >> 31;
        const int row  = __ldg(&cyrows[e]);
        const int prev = (e > 0) ? __ldg(&cyrows[e - 1]) : -1;
        const unsigned flag = (row != prev) ? 0x80000000u : 0u;
        sh[j] = (unsigned)(idx * B_UINT4) | (sbit << 29) | flag;
    }
    __syncthreads();

    // Warp 0: ballot-scan row starts over the 128-entry window.
    if (wid == 0) {
        int m = 0;
        #pragma unroll
        for (int cgrp = 0; cgrp < P2_EXT / 32; ++cgrp) {
            const int j = cgrp * 32 + lane;
            const bool f = (j < n) && (sh[j] & 0x80000000u);
            const unsigned bal = __ballot_sync(0xFFFFFFFFu, f);
            if (f) rs[m + __popc(bal & ((1u << lane) - 1u))] = (short)j;
            m += __popc(bal);
        }
        if (lane == 0) {
            const int lim = (P2_BASE < n) ? P2_BASE : n;
            int mo = 0;
            while (mo < m && rs[mo] < lim) ++mo;   // owned = starts in [0, lim)
            sh_cnt[0] = m;
            sh_cnt[1] = mo;
        }
    }
    __syncthreads();
    const int m  = sh_cnt[0];
    const int mo = sh_cnt[1];

    const __half2 h2z = __half2half2(__ushort_as_half(0));
    float sum = 0.0f;

    // Warps round-robin over owned rows.
    for (int k = wid; k < mo; k += 2) {
        const int st = rs[k];
        const int en = (k + 1 < m) ? rs[k + 1] : n;

        __half2 a0 = h2z, a1 = h2z, a2 = h2z, a3 = h2z;

        #pragma unroll 2
        for (int j = st; j < en; ++j) {
            const unsigned meta = sh[j];
            const unsigned mask = ((meta >> 29) & 1u) * 0x80008000u;
            uint4 u = g_AT4[(size_t)(meta & 0x1FFFFFFFu) + lane];
            u.x ^= mask; u.y ^= mask; u.z ^= mask; u.w ^= mask;
            a0 = __hadd2(a0, *reinterpret_cast<__half2*>(&u.x));
            a1 = __hadd2(a1, *reinterpret_cast<__half2*>(&u.y));
            a2 = __hadd2(a2, *reinterpret_cast<__half2*>(&u.z));
            a3 = __hadd2(a3, *reinterpret_cast<__half2*>(&u.w));
        }

        // Fallback (statistically never taken): last staged row continues
        // past the window -> finish from global memory.
        if (k == m - 1 && base + n < E) {
            const int row = __ldg(&cyrows[base + st]);
            for (int e = base + n; e < E && __ldg(&cyrows[e]) == row; ++e) {
                const int idx = __ldg(&cyinds[e]);
                const unsigned mask =
                    (__float_as_uint(__ldg(&cysigns[e])) >> 31) * 0x80008000u;
                uint4 u = g_AT4[(size_t)idx * B_UINT4 + lane];
                u.x ^= mask; u.y ^= mask; u.z ^= mask; u.w ^= mask;
                a0 = __hadd2(a0, *reinterpret_cast<__half2*>(&u.x));
                a1 = __hadd2(a1, *reinterpret_cast<__half2*>(&u.y));
                a2 = __hadd2(a2, *reinterpret_cast<__half2*>(&u.z));
                a3 = __hadd2(a3, *reinterpret_cast<__half2*>(&u.w));
            }
        }

        const float2 f0 = __half22float2(a0);
        const float2 f1 = __half22float2(a1);
        const float2 f2 = __half22float2(a2);
        const float2 f3 = __half22float2(a3);
        sum += fabsf(f0.x) + fabsf(f0.y) + fabsf(f1.x) + fabsf(f1.y)
             + fabsf(f2.x) + fabsf(f2.y) + fabsf(f3.x) + fabsf(f3.y);
    }

    // Reduce: 2 warps.
    #pragma unroll
    for (int off = 16; off > 0; off >>= 1)
        sum += __shfl_down_sync(0xFFFFFFFFu, sum, off);
    if (lane == 0) warp_sums[wid] = sum;
    __syncthreads();
    if (tid == 0) {
        const float w = warp_sums[0] + warp_sums[1];
        if (w != 0.0f) atomicAdd(&g_accum, (double)w);
        __threadfence();
        const unsigned ticket = atomicAdd(&g_done, 1u);
        if (ticket == (unsigned)(gridDim.x - 1)) {
            __threadfence();
            const double total = *((volatile double*)&g_accum);
            out[0] = (float)(total * (1.0 / ((double)N_CYC * (double)B_DIM)));
        }
    }
}

extern "C" void kernel_launch(void* const* d_in, const int* in_sizes, int n_in,
                              void* d_out, int out_size) {
    const float* c       = (const float*)d_in[0];
    const float* s       = (const float*)d_in[1];
    const float* cysigns = (const float*)d_in[2];
    const int*   cyinds  = (const int*)d_in[3];
    const int*   cyrows  = (const int*)d_in[4];
    float* out = (float*)d_out;
    const int E = in_sizes[4];

    dim3 t1(16, 16);
    dim3 g1((NB_DIM + 63) / 64, B_DIM / 64);
    phase1_atan2_transpose<<<g1, t1>>>(c, s);

    const int g2 = (E + P2_BASE - 1) / P2_BASE;
    phase2_cycle_sum<<<g2, P2_THREADS>>>(cysigns, cyinds, cyrows, out, E);
}

// round 13
// speedup vs baseline: 1.1164x; 1.1096x over previous
#include <cuda_runtime.h>
#include <cuda_fp16.h>
#include <math.h>

#define B_DIM      256
#define B_HALF2    (B_DIM / 2)       // 128 uints per A_T row = 512 B
#define B_UINT2    64                // 64 uint2 per row
#define NB_DIM     50000
#define N_CYC      20000
#define P2_THREADS 64                // thread = one uint2 lane (8 B) of the row
#define P2_BASE    64                // entries owned per phase-2 block
#define P2_EXT     160               // staged entries (64 + 96 slack)
#define BATCH      8                 // gathers kept in flight per warp

// A_T[i] = 256 batch angles as fp16; row = 64 uint2 = 512 B.
__device__ uint2    g_AT2[(size_t)NB_DIM * B_UINT2];   // 25.6 MB
__device__ double   g_accum;
__device__ unsigned g_done;

// ---------------------------------------------------------------------------
// Branchless fast atan2 (minimax, |err| < 1e-5 rad; subdominant to fp16
// storage quantization).
// ---------------------------------------------------------------------------
__device__ __forceinline__ float fast_atan2f(float y, float x) {
    const float ax = fabsf(x), ay = fabsf(y);
    const float mx = fmaxf(ax, ay), mn = fminf(ax, ay);
    const float t = __fdividef(mn, mx);
    const float a = t * t;
    float r = fmaf(a, 0.0208351f, -0.0851330f);
    r = fmaf(r, a, 0.1801410f);
    r = fmaf(r, a, -0.3302995f);
    r = fmaf(r, a, 0.9998660f);
    r = r * t;
    if (ay > ax)  r = 1.57079632679f - r;
    if (x < 0.0f) r = 3.14159265359f - r;
    return copysignf(r, y);
}

__device__ __forceinline__ unsigned pack_pair(float a, float b) {
    __half2 h = __floats2half2_rn(a, b);
    return *reinterpret_cast<unsigned*>(&h);
}

// ---------------------------------------------------------------------------
// Phase 1: A_T[i][b] = (half)atan2(s[b,i], c[b,i]).
// Tile 64 i x 64 b, block (16,16): thread handles i-quad x TWO batch-pairs
// (8x LDG.128 front-batched, 16 atan2). c/s loaded streaming (__ldcs) so
// they don't evict A_T from L2. Transpose via smem, coalesced 128B rows out.
// ---------------------------------------------------------------------------
__global__ void phase1_atan2_transpose(const float* __restrict__ c,
                                       const float* __restrict__ s) {
    __shared__ unsigned tile[64][33];

    const int tx = threadIdx.x;          // 0..15 : i-quad
    const int ty = threadIdx.y;          // 0..15 : base b-pair
    const int i_base = blockIdx.x * 64;
    const int b_base = blockIdx.y * 64;
    const int i0 = i_base + tx * 4;

    if (i0 < NB_DIM) {                   // i0%4==0, NB_DIM%4==0 -> safe float4
        const int bA = b_base + 2 * ty;
        const int bB = b_base + 2 * (ty + 16);

        const float4* cp = (const float4*)(c + i0);
        const float4* sp = (const float4*)(s + i0);
        const size_t q = (size_t)NB_DIM / 4;

        const float4 cA1 = __ldcs(cp + (size_t)bA * q);
        const float4 sA1 = __ldcs(sp + (size_t)bA * q);
        const float4 cA2 = __ldcs(cp + (size_t)(bA + 1) * q);
        const float4 sA2 = __ldcs(sp + (size_t)(bA + 1) * q);
        const float4 cB1 = __ldcs(cp + (size_t)bB * q);
        const float4 sB1 = __ldcs(sp + (size_t)bB * q);
        const float4 cB2 = __ldcs(cp + (size_t)(bB + 1) * q);
        const float4 sB2 = __ldcs(sp + (size_t)(bB + 1) * q);

        tile[tx*4+0][ty]    = pack_pair(fast_atan2f(sA1.x, cA1.x), fast_atan2f(sA2.x, cA2.x));
        tile[tx*4+1][ty]    = pack_pair(fast_atan2f(sA1.y, cA1.y), fast_atan2f(sA2.y, cA2.y));
        tile[tx*4+2][ty]    = pack_pair(fast_atan2f(sA1.z, cA1.z), fast_atan2f(sA2.z, cA2.z));
        tile[tx*4+3][ty]    = pack_pair(fast_atan2f(sA1.w, cA1.w), fast_atan2f(sA2.w, cA2.w));
        tile[tx*4+0][ty+16] = pack_pair(fast_atan2f(sB1.x, cB1.x), fast_atan2f(sB2.x, cB2.x));
        tile[tx*4+1][ty+16] = pack_pair(fast_atan2f(sB1.y, cB1.y), fast_atan2f(sB2.y, cB2.y));
        tile[tx*4+2][ty+16] = pack_pair(fast_atan2f(sB1.z, cB1.z), fast_atan2f(sB2.z, cB2.z));
        tile[tx*4+3][ty+16] = pack_pair(fast_atan2f(sB1.w, cB1.w), fast_atan2f(sB2.w, cB2.w));
    }
    __syncthreads();

    const int tid  = ty * 16 + tx;
    const int w    = tid >> 5;
    const int lane = tid & 31;
    unsigned* ATu = (unsigned*)g_AT2;
    #pragma unroll
    for (int k = 0; k < 8; ++k) {
        const int r  = w + 8 * k;
        const int gi = i_base + r;
        if (gi < NB_DIM)
            ATu[(size_t)gi * B_HALF2 + (b_base >> 1) + lane] = tile[r][lane];
    }

    if (blockIdx.x == 0 && blockIdx.y == 0 && tid == 0) {
        g_accum = 0.0;
        g_done = 0u;
    }
}

// ---------------------------------------------------------------------------
// Phase 2: R7 shape (64 entries/block, 64 threads, thread = uint2 lane) with
// the latency chain broken: inner loop runs in BATCH=8 chunks -- first 8
// independent gathers are issued (no branch between them), then the branchy
// flush/XOR/HADD2 consumption pass runs on in-flight data. MLP ~8 per warp.
// Last block writes the final scalar.
// ---------------------------------------------------------------------------
__global__ __launch_bounds__(P2_THREADS) void phase2_cycle_sum(
    const float* __restrict__ cysigns,
    const int*   __restrict__ cyinds,
    const int*   __restrict__ cyrows,
    float*       __restrict__ out,
    int E) {

    __shared__ uint2 sh[P2_EXT];
    __shared__ int   sh_se[2];
    __shared__ float warp_sums[2];

    const int tid  = threadIdx.x;
    const int base = blockIdx.x * P2_BASE;
    const int n    = min(P2_EXT, E - base);

    // Stage: .x = idx*64 | rowchange<<31, .y = sign xor-mask for half2.
    for (int j = tid; j < n; j += P2_THREADS) {
        const int e = base + j;
        const int idx = __ldg(&cyinds[e]);
        unsigned m = __float_as_uint(__ldg(&cysigns[e])) & 0x80000000u;
        m |= m >> 16;
        const int row  = __ldg(&cyrows[e]);
        const int prev = (e > 0) ? __ldg(&cyrows[e - 1]) : -1;
        const unsigned flag = (row != prev) ? 0x80000000u : 0u;
        sh[j] = make_uint2((unsigned)(idx * B_UINT2) | flag, m);
    }
    __syncthreads();

    if (tid == 0) {
        int st = 0;
        while (st < n && !(sh[st].x & 0x80000000u)) ++st;
        int en = (P2_BASE < n) ? P2_BASE : n;
        while (en < n && !(sh[en].x & 0x80000000u)) ++en;
        sh_se[0] = st;
        sh_se[1] = en;
    }
    __syncthreads();
    const int st = sh_se[0];
    const int en = sh_se[1];

    const __half2 h2z = __half2half2(__ushort_as_half(0));
    __half2 acc0 = h2z, acc1 = h2z;
    float sum = 0.0f;

    for (int j0 = st; j0 < en; j0 += BATCH) {
        const int cnt = min(BATCH, en - j0);

        // Pass A: issue all gathers (independent, no branches between).
        uint2 p[BATCH];
        uint2 v[BATCH];
        #pragma unroll
        for (int k = 0; k < BATCH; ++k) {
            if (k < cnt) {
                p[k] = sh[j0 + k];
                v[k] = g_AT2[(size_t)(p[k].x & 0x7FFFFFFFu) + tid];
            }
        }

        // Pass B: consume (branch is fine -- loads already in flight).
        #pragma unroll
        for (int k = 0; k < BATCH; ++k) {
            if (k < cnt) {
                if (p[k].x & 0x80000000u) {     // uniform across block
                    const float2 f0 = __half22float2(acc0);
                    const float2 f1 = __half22float2(acc1);
                    sum += fabsf(f0.x) + fabsf(f0.y) + fabsf(f1.x) + fabsf(f1.y);
                    acc0 = h2z; acc1 = h2z;
                }
                uint2 u = v[k];
                u.x ^= p[k].y;
                u.y ^= p[k].y;
                acc0 = __hadd2(acc0, *reinterpret_cast<__half2*>(&u.x));
                acc1 = __hadd2(acc1, *reinterpret_cast<__half2*>(&u.y));
            }
        }
    }

    // Fallback (statistically never taken): the block's last row extends
    // beyond the staged window -> finish it straight from global memory.
    if (en == n && st < en && base + n < E) {
        const int row = __ldg(&cyrows[base + n - 1]);
        for (int e = base + n; e < E && __ldg(&cyrows[e]) == row; ++e) {
            const int idx = __ldg(&cyinds[e]);
            unsigned m = __float_as_uint(__ldg(&cysigns[e])) & 0x80000000u;
            m |= m >> 16;
            uint2 u = g_AT2[(size_t)idx * B_UINT2 + tid];
            u.x ^= m;
            u.y ^= m;
            acc0 = __hadd2(acc0, *reinterpret_cast<__half2*>(&u.x));
            acc1 = __hadd2(acc1, *reinterpret_cast<__half2*>(&u.y));
        }
    }

    {   // final row flush
        const float2 f0 = __half22float2(acc0);
        const float2 f1 = __half22float2(acc1);
        sum += fabsf(f0.x) + fabsf(f0.y) + fabsf(f1.x) + fabsf(f1.y);
    }

    // Block reduction (2 warps)
    #pragma unroll
    for (int off = 16; off > 0; off >>= 1)
        sum += __shfl_down_sync(0xFFFFFFFFu, sum, off);
    const int lane = tid & 31, wid = tid >> 5;
    if (lane == 0) warp_sums[wid] = sum;
    __syncthreads();
    if (tid == 0) {
        const float w = warp_sums[0] + warp_sums[1];
        if (w != 0.0f) atomicAdd(&g_accum, (double)w);
        __threadfence();
        const unsigned ticket = atomicAdd(&g_done, 1u);
        if (ticket == (unsigned)(gridDim.x - 1)) {
            __threadfence();
            const double total = *((volatile double*)&g_accum);
            out[0] = (float)(total * (1.0 / ((double)N_CYC * (double)B_DIM)));
        }
    }
}

extern "C" void kernel_launch(void* const* d_in, const int* in_sizes, int n_in,
                              void* d_out, int out_size) {
    const float* c       = (const float*)d_in[0];
    const float* s       = (const float*)d_in[1];
    const float* cysigns = (const float*)d_in[2];
    const int*   cyinds  = (const int*)d_in[3];
    const int*   cyrows  = (const int*)d_in[4];
    float* out = (float*)d_out;
    const int E = in_sizes[4];

    dim3 t1(16, 16);
    dim3 g1((NB_DIM + 63) / 64, B_DIM / 64);
    phase1_atan2_transpose<<<g1, t1>>>(c, s);

    const int g2 = (E + P2_BASE - 1) / P2_BASE;
    phase2_cycle_sum<<<g2, P2_THREADS>>>(cysigns, cyinds, cyrows, out, E);
}